// round 10
// baseline (speedup 1.0000x reference)
#include <cuda_runtime.h>
#include <cstddef>

#define NB 1024          // 32*32 nodes per time slice
#define NT 9
#define TN (NT * NB)     // 9216
#define PRE_D 36         // 9 diag blocks * 4 row-chunks of 256
#define PRE_O 32         // 8 offdiag slices * 4 chunks
#define PRE_CTAS 68

// Compact band scratch (producer -> consumer, L2-resident ~1.2 MB).
// g_D[i][p][slot25]: diag value at delta = ey*32+ex, slot=(ey+2)*5+(ex+2)
// g_O[t][p][j9]:     offdiag value at delta, j = (dy+1)*3+(dx+1)
__device__ float g_D[9 * NB * 25];
__device__ float g_O[8 * NB * 9];
__device__ int   g_done;            // producer completion counter

// ---------------------------------------------------------------------------
// Reset kernel: stream-ordered producer-counter reset (graph-friendly,
// no host-side symbol APIs).
// ---------------------------------------------------------------------------
__global__ void k_reset() { g_done = 0; }

// ---------------------------------------------------------------------------
// Per-node 9-point stencil coefficients of A at time slice ts.
// j = (dy+1)*3 + (dx+1); Dirichlet-invalid moves = exact 0.
// ---------------------------------------------------------------------------
__device__ __forceinline__ void coef9(const float* __restrict__ kappa,
                                      const float* __restrict__ m,
                                      const float* __restrict__ H,
                                      int n, int ts, float* c) {
    float kap = kappa[n * NT + ts];
    float k2  = kap * kap;
    float m1  = m[(0 * NB + n) * NT + ts];
    float m2  = m[(1 * NB + n) * NT + ts];
    float H11 = H[(0 * NB + n) * NT + ts];
    float H12 = H[(1 * NB + n) * NT + ts];
    float H22 = H[(3 * NB + n) * NT + ts];

    int ix = n & 31, iy = n >> 5;
    bool xm = ix > 0, xp = ix < 31, ym = iy > 0, yp = iy < 31;

    c[4] = k2 + 2.0f * H11 + 2.0f * H22;
    c[5] = xp         ? ( 0.5f * m1 - H11) : 0.0f;
    c[3] = xm         ? (-0.5f * m1 - H11) : 0.0f;
    c[7] = yp         ? ( 0.5f * m2 - H22) : 0.0f;
    c[1] = ym         ? (-0.5f * m2 - H22) : 0.0f;
    c[8] = (xp && yp) ? (-0.5f * H12)      : 0.0f;
    c[2] = (xp && ym) ? ( 0.5f * H12)      : 0.0f;
    c[6] = (xm && yp) ? ( 0.5f * H12)      : 0.0f;
    c[0] = (xm && ym) ? (-0.5f * H12)      : 0.0f;
}

// Band lookups against the per-row staged table (smem).
__device__ __forceinline__ float dgs(const float* __restrict__ Dp, int d) {
    if (d < -66 || d > 66) return 0.0f;
    int ey = ((d + 68) >> 5) - 2;
    int ex = d - (ey << 5);
    if (ex < -2 || ex > 2) return 0.0f;
    return Dp[(ey + 2) * 5 + ex + 2];
}
__device__ __forceinline__ float ods(const float* __restrict__ Op, int d) {
    unsigned de = (unsigned)(d + 33);
    if (de > 66u) return 0.0f;
    unsigned rr = de & 31u;
    if (rr > 2u) return 0.0f;
    return Op[(de >> 5) * 3 + rr];
}

// ---------------------------------------------------------------------------
// Single fused kernel, 32-reg budget enforced.
//   CTAs 0..67:      producers — compute compact band scratch, signal g_done.
//                    Diag slots computed serially with 2 scalar accumulators
//                    (no register arrays -> no reg contamination).
//   CTAs 68..9283:   consumers — one output row each: stream 6 zero blocks,
//                    wait for g_done, stage 43 band floats to smem, stream
//                    the 3 band blocks. Every output byte written once.
// ---------------------------------------------------------------------------
__global__ __launch_bounds__(256, 8)
void k_all(const float* __restrict__ kappa,
           const float* __restrict__ m,
           const float* __restrict__ H,
           float* __restrict__ out) {
    int cb  = blockIdx.x;
    int tid = threadIdx.x;

    __shared__ float sb[388 * 9];       // producers: coef window (13.6 KB)
    __shared__ float sBand[48];         // consumers: [0..24] D, [25..33] L, [34..42] R

    if (cb < PRE_CTAS) {
        // ========================= producers =========================
        if (cb < PRE_D) {
            // ---- diag block i, rows p0..p0+255, plain-A window ----
            int i = cb >> 2, chunk = cb & 3, p0 = chunk << 8;
            int t = (i == 0) ? 0 : i - 1;
            int base = max(0, p0 - 66);
            int hi   = min(NB, p0 + 256 + 66);
            int cnt  = hi - base;

            for (int idx = tid; idx < cnt; idx += 256) {
                float c[9];
                coef9(kappa, m, H, base + idx, t + 1, c);
#pragma unroll
                for (int j = 0; j < 9; j++) sb[idx * 9 + j] = c[j];
            }
            __syncthreads();

            int p = p0 + tid;
            float* dst = g_D + ((size_t)i * NB + p) * 25;
            float dadd = (i < 8) ? 1.05f : 0.05f;

#pragma unroll
            for (int slot = 0; slot < 25; slot++) {
                int ey = slot / 5 - 2, ex = slot % 5 - 2;
                int delta = ey * 32 + ex;
                int q = p + delta;
                float v = 0.0f;
                if (q >= 0 && q < NB) {
                    if (i == 0) {
                        // (A^T A)[p][q] = sum_r A[r][p]*A[r][q]
                        float acc = 0.0f;
#pragma unroll
                        for (int j = 0; j < 9; j++) {
                            int dy = j / 3 - 1, dx = j % 3 - 1;
                            int rr = p + dy * 32 + dx;
                            if (rr < 0 || rr >= NB) continue;
                            int ddy = ey - dy, ddx = ex - dx;
                            if (ddy < -1 || ddy > 1 || ddx < -1 || ddx > 1) continue;
                            int j2 = (ddy + 1) * 3 + (ddx + 1);
                            acc += sb[(rr - base) * 9 + (8 - j)] *
                                   sb[(rr - base) * 9 + j2];
                        }
                        v = acc + ((delta == 0) ? 1.05f : 0.0f);
                    } else {
                        // 0.5*(MM + MM^T)[p][q], MM = (I+A)^2
                        float mmpq = 0.0f, mmqp = 0.0f;
#pragma unroll
                        for (int j = 0; j < 9; j++) {
                            int dy = j / 3 - 1, dx = j % 3 - 1;
                            {   // p -> rr -> q
                                int rr = p + dy * 32 + dx;
                                int ddy = ey - dy, ddx = ex - dx;
                                if (rr >= 0 && rr < NB &&
                                    ddy >= -1 && ddy <= 1 && ddx >= -1 && ddx <= 1) {
                                    int j2 = (ddy + 1) * 3 + (ddx + 1);
                                    float a = sb[(p - base) * 9 + j]   + ((j  == 4) ? 1.0f : 0.0f);
                                    float b = sb[(rr - base) * 9 + j2] + ((j2 == 4) ? 1.0f : 0.0f);
                                    mmpq += a * b;
                                }
                            }
                            {   // q -> ss -> p
                                int ss = q + dy * 32 + dx;
                                int ddy = -ey - dy, ddx = -ex - dx;
                                if (ss >= 0 && ss < NB &&
                                    ddy >= -1 && ddy <= 1 && ddx >= -1 && ddx <= 1) {
                                    int j2 = (ddy + 1) * 3 + (ddx + 1);
                                    float a = sb[(q - base) * 9 + j]   + ((j  == 4) ? 1.0f : 0.0f);
                                    float b = sb[(ss - base) * 9 + j2] + ((j2 == 4) ? 1.0f : 0.0f);
                                    mmqp += a * b;
                                }
                            }
                        }
                        v = 0.5f * (mmpq + mmqp) + ((delta == 0) ? dadd : 0.0f);
                    }
                }
                dst[slot] = v;
            }
        } else {
            // ---- offdiag slice t, rows p0..p0+255 ----
            int cb2 = cb - PRE_D;
            int t = cb2 >> 2, chunk = cb2 & 3, p0 = chunk << 8;
            int base = max(0, p0 - 33);
            int hi   = min(NB, p0 + 256 + 33);
            int cnt  = hi - base;

            for (int idx = tid; idx < cnt; idx += 256) {
                float c[9];
                coef9(kappa, m, H, base + idx, t + 1, c);
#pragma unroll
                for (int j = 0; j < 9; j++) sb[idx * 9 + j] = c[j];
            }
            __syncthreads();

            int p = p0 + tid;
            const float* ap = sb + (p - base) * 9;
            float* dst = g_O + ((size_t)t * NB + p) * 9;
#pragma unroll
            for (int j = 0; j < 9; j++) {
                int dy = j / 3 - 1, dx = j % 3 - 1;
                int q = p + dy * 32 + dx;
                float v = 0.0f;
                if (q >= 0 && q < NB) {
                    float add = (j == 4) ? 2.0f : 0.0f;   // both invM get +I
                    v = -0.5f * (ap[j] + sb[(q - base) * 9 + (8 - j)] + add);
                }
                dst[j] = v;
            }
        }
        __syncthreads();
        if (tid == 0) {
            __threadfence();
            atomicAdd(&g_done, 1);
        }
        return;
    }

    // ========================= consumers =========================
    int r = cb - PRE_CTAS;              // output row 0..9215
    int i = r >> 10;
    int p = r & (NB - 1);
    float4* rowp = (float4*)(out + (size_t)r * TN);
    float4 z = make_float4(0.f, 0.f, 0.f, 0.f);

    // 1) stream the non-band column blocks (stores drain while we wait)
#pragma unroll
    for (int j = 0; j < 9; j++) {
        if (j < i - 1 || j > i + 1)
            __stcs(rowp + j * 256 + tid, z);
    }

    // 2) wait for producers (always resident in wave 1: 68 << capacity)
    if (tid == 0) {
        while (atomicAdd(&g_done, 0) < PRE_CTAS) __nanosleep(64);
    }
    __syncthreads();

    // 3) stage this row's 43 band values into smem (coalesced L2 reads)
    if (tid < 25) {
        sBand[tid] = g_D[((size_t)i * NB + p) * 25 + tid];
    } else if (tid >= 32 && tid < 41) {
        sBand[tid - 7] = (i > 0)
            ? g_O[((size_t)(i - 1) * NB + p) * 9 + tid - 32] : 0.0f;
    } else if (tid >= 64 && tid < 73) {
        sBand[tid - 30] = (i < 8)
            ? g_O[((size_t)i * NB + p) * 9 + tid - 64] : 0.0f;
    }
    __syncthreads();

    // 4) stream the band column blocks
    int q0 = tid << 2;
    int d0 = q0 - p;

    {   // diag block i
        float4 v = z;
        if (d0 + 3 >= -66 && d0 <= 66) {
            v.x = dgs(sBand, d0);
            v.y = dgs(sBand, d0 + 1);
            v.z = dgs(sBand, d0 + 2);
            v.w = dgs(sBand, d0 + 3);
        }
        __stcs(rowp + i * 256 + tid, v);
    }
    if (i > 0) {
        float4 v = z;
        if (d0 + 3 >= -33 && d0 <= 33) {
            v.x = ods(sBand + 25, d0);
            v.y = ods(sBand + 25, d0 + 1);
            v.z = ods(sBand + 25, d0 + 2);
            v.w = ods(sBand + 25, d0 + 3);
        }
        __stcs(rowp + (i - 1) * 256 + tid, v);
    }
    if (i < 8) {
        float4 v = z;
        if (d0 + 3 >= -33 && d0 <= 33) {
            v.x = ods(sBand + 34, d0);
            v.y = ods(sBand + 34, d0 + 1);
            v.z = ods(sBand + 34, d0 + 2);
            v.w = ods(sBand + 34, d0 + 3);
        }
        __stcs(rowp + (i + 1) * 256 + tid, v);
    }
}

// ---------------------------------------------------------------------------
// Launcher. Inputs: kappa, m, H, tau (unused). Output: fp32 [1, 9216, 9216].
// ---------------------------------------------------------------------------
extern "C" void kernel_launch(void* const* d_in, const int* in_sizes, int n_in,
                              void* d_out, int out_size) {
    const float* kappa = (const float*)d_in[0];
    const float* m     = (const float*)d_in[1];
    const float* H     = (const float*)d_in[2];
    float* out = (float*)d_out;

    k_reset<<<1, 1>>>();                       // stream-ordered counter reset
    k_all<<<PRE_CTAS + TN, 256>>>(kappa, m, H, out);
}

// round 11
// speedup vs baseline: 1.1262x; 1.1262x over previous
#include <cuda_runtime.h>
#include <cstddef>

#define NB 1024          // 32*32 nodes per time slice
#define NT 9
#define TN (NT * NB)     // 9216
// Per-CTA: 2 adjacent rows of the same block row.
// Shared layout sizes
#define W0MAX 134        // slice-t0 window nodes (p0-66 .. p0+67)
#define BSTRIDE 272      // per-row band array: [0..135]=D, [136..203]=L, [204..271]=R

// ---------------------------------------------------------------------------
// Per-node 9-point stencil coefficients of A at time slice ts.
// j = (dy+1)*3 + (dx+1); Dirichlet-invalid moves = exact 0.
// ---------------------------------------------------------------------------
__device__ __forceinline__ void coef9(const float* __restrict__ kappa,
                                      const float* __restrict__ m,
                                      const float* __restrict__ H,
                                      int n, int ts, float* c) {
    float kap = kappa[n * NT + ts];
    float k2  = kap * kap;
    float m1  = m[(0 * NB + n) * NT + ts];
    float m2  = m[(1 * NB + n) * NT + ts];
    float H11 = H[(0 * NB + n) * NT + ts];
    float H12 = H[(1 * NB + n) * NT + ts];
    float H22 = H[(3 * NB + n) * NT + ts];

    int ix = n & 31, iy = n >> 5;
    bool xm = ix > 0, xp = ix < 31, ym = iy > 0, yp = iy < 31;

    c[4] = k2 + 2.0f * H11 + 2.0f * H22;
    c[5] = xp         ? ( 0.5f * m1 - H11) : 0.0f;
    c[3] = xm         ? (-0.5f * m1 - H11) : 0.0f;
    c[7] = yp         ? ( 0.5f * m2 - H22) : 0.0f;
    c[1] = ym         ? (-0.5f * m2 - H22) : 0.0f;
    c[8] = (xp && yp) ? (-0.5f * H12)      : 0.0f;
    c[2] = (xp && ym) ? ( 0.5f * H12)      : 0.0f;
    c[6] = (xm && yp) ? ( 0.5f * H12)      : 0.0f;
    c[0] = (xm && ym) ? (-0.5f * H12)      : 0.0f;
}

// ---------------------------------------------------------------------------
// Single self-contained kernel: one CTA per 2 adjacent output rows.
//   1) stream 6 non-band column blocks per row (zeros; drain during math)
//   2) build coef windows: slice t0 (134 nodes) + slice i (12 nodes, 3 segs)
//   3) 86 threads compute band slots into direct-indexed pre-zeroed arrays
//   4) stream 3 band column blocks per row (add+cmp+LDS per element)
// Every output byte written exactly once; no inter-CTA dependency.
// ---------------------------------------------------------------------------
__global__ __launch_bounds__(256)
void k_all(const float* __restrict__ kappa,
           const float* __restrict__ m,
           const float* __restrict__ H,
           float* __restrict__ out) {
    int bc  = blockIdx.x;               // 0..4607
    int r0  = bc << 1;                  // first row
    int i   = r0 >> 10;                 // block row (rows never straddle)
    int p0  = r0 & (NB - 1);
    int tid = threadIdx.x;
    float4 z = make_float4(0.f, 0.f, 0.f, 0.f);

    // ---- 1) zero blocks for both rows ----
#pragma unroll
    for (int rr = 0; rr < 2; rr++) {
        float4* rowp = (float4*)(out + (size_t)(r0 + rr) * TN);
#pragma unroll
        for (int j = 0; j < 9; j++) {
            if (j < i - 1 || j > i + 1)
                __stcs(rowp + j * 256 + tid, z);
        }
    }

    // ---- 2) build coefficient windows + zero band arrays ----
    __shared__ float sA0[W0MAX * 9];    // slice t0, nodes wbase..wbase+cnt0-1
    __shared__ float sA1[12 * 9];       // slice i, 3 segments of 4 nodes
    __shared__ float sBand[2][BSTRIDE];

    int t0    = (i == 0) ? 0 : (i - 1);
    int wbase = max(0, p0 - 66);
    int whi   = min(NB, p0 + 68);
    int cnt0  = whi - wbase;
    bool needA1 = (i >= 1 && i <= 7);

    for (int k = tid; k < 2 * BSTRIDE; k += 256)
        ((float*)sBand)[k] = 0.0f;

    int tot = cnt0 + (needA1 ? 12 : 0);
    for (int k = tid; k < tot; k += 256) {
        float c[9];
        if (k < cnt0) {
            coef9(kappa, m, H, wbase + k, t0 + 1, c);
            float* dst = sA0 + k * 9;
#pragma unroll
            for (int j = 0; j < 9; j++) dst[j] = c[j];
        } else {
            int kk = k - cnt0;                  // 0..11
            int seg = kk >> 2;
            int node = p0 + seg * 32 - 33 + (kk & 3);
            float* dst = sA1 + kk * 9;
            if (node >= 0 && node < NB) {
                coef9(kappa, m, H, node, i + 1, c);
#pragma unroll
                for (int j = 0; j < 9; j++) dst[j] = c[j];
            } else {
#pragma unroll
                for (int j = 0; j < 9; j++) dst[j] = 0.0f;
            }
        }
    }
    __syncthreads();

    // ---- 3) band slot computation (86 active threads) ----
    int rr = -1, s = 0;
    if (tid < 43)                    { rr = 0; s = tid; }
    else if (tid >= 64 && tid < 107) { rr = 1; s = tid - 64; }

    if (rr >= 0) {
        int p = p0 + rr;
        if (s < 25) {
            // diag slot: delta = ey*32 + ex
            int ey = s / 5 - 2, ex = s % 5 - 2;
            int delta = ey * 32 + ex;
            int q = p + delta;
            if (q >= 0 && q < NB) {
                float v;
                if (i == 0) {
                    // (A^T A)[p][q] = sum_r A[r][p]*A[r][q]
                    float acc = 0.0f;
#pragma unroll
                    for (int j = 0; j < 9; j++) {
                        int dy = j / 3 - 1, dx = j % 3 - 1;
                        int rn = p + dy * 32 + dx;
                        if (rn < 0 || rn >= NB) continue;
                        int ddy = ey - dy, ddx = ex - dx;
                        if (ddy < -1 || ddy > 1 || ddx < -1 || ddx > 1) continue;
                        int j2 = (ddy + 1) * 3 + (ddx + 1);
                        acc += sA0[(rn - wbase) * 9 + (8 - j)] *
                               sA0[(rn - wbase) * 9 + j2];
                    }
                    v = acc + ((delta == 0) ? 1.05f : 0.0f);
                } else {
                    // 0.5*(MM + MM^T)[p][q],  MM = (I+A)^2 on slice t0
                    float mmpq = 0.0f, mmqp = 0.0f;
#pragma unroll
                    for (int j = 0; j < 9; j++) {
                        int dy = j / 3 - 1, dx = j % 3 - 1;
                        {   // p -> rn -> q
                            int rn = p + dy * 32 + dx;
                            int ddy = ey - dy, ddx = ex - dx;
                            if (rn >= 0 && rn < NB &&
                                ddy >= -1 && ddy <= 1 && ddx >= -1 && ddx <= 1) {
                                int j2 = (ddy + 1) * 3 + (ddx + 1);
                                float a = sA0[(p - wbase) * 9 + j]   + ((j  == 4) ? 1.0f : 0.0f);
                                float b = sA0[(rn - wbase) * 9 + j2] + ((j2 == 4) ? 1.0f : 0.0f);
                                mmpq += a * b;
                            }
                        }
                        {   // q -> sn -> p
                            int sn = q + dy * 32 + dx;
                            int ddy = -ey - dy, ddx = -ex - dx;
                            if (sn >= 0 && sn < NB &&
                                ddy >= -1 && ddy <= 1 && ddx >= -1 && ddx <= 1) {
                                int j2 = (ddy + 1) * 3 + (ddx + 1);
                                float a = sA0[(q - wbase) * 9 + j]   + ((j  == 4) ? 1.0f : 0.0f);
                                float b = sA0[(sn - wbase) * 9 + j2] + ((j2 == 4) ? 1.0f : 0.0f);
                                mmqp += a * b;
                            }
                        }
                    }
                    v = 0.5f * (mmpq + mmqp) +
                        ((delta == 0) ? ((i < 8) ? 1.05f : 0.05f) : 0.0f);
                }
                sBand[rr][delta + 66] = v;
            }
        } else if (s < 34) {
            // left offdiag (slice t0 = i-1): -0.5*(B + B^T)[p][q]
            int j = s - 25;
            int dy = j / 3 - 1, dx = j % 3 - 1;
            int delta = dy * 32 + dx;
            int q = p + delta;
            if (i > 0 && q >= 0 && q < NB) {
                float add = (j == 4) ? 2.0f : 0.0f;
                float v = -0.5f * (sA0[(p - wbase) * 9 + j] +
                                   sA0[(q - wbase) * 9 + (8 - j)] + add);
                sBand[rr][136 + delta + 33] = v;
            }
        } else {
            // right offdiag (slice i): sA1 (12-node map) for 1<=i<=7, sA0 for i=0
            int j = s - 34;
            int dy = j / 3 - 1, dx = j % 3 - 1;
            int delta = dy * 32 + dx;
            int q = p + delta;
            if (i < 8 && q >= 0 && q < NB) {
                float a, b;
                if (i == 0) {
                    a = sA0[(p - wbase) * 9 + j];
                    b = sA0[(q - wbase) * 9 + (8 - j)];
                } else {
                    int offp = p - p0 + 33;
                    int offq = q - p0 + 33;
                    int ip = (offp >> 5) * 4 + (offp & 31);
                    int iq = (offq >> 5) * 4 + (offq & 31);
                    a = sA1[ip * 9 + j];
                    b = sA1[iq * 9 + (8 - j)];
                }
                float add = (j == 4) ? 2.0f : 0.0f;
                float v = -0.5f * (a + b + add);
                sBand[rr][204 + delta + 33] = v;
            }
        }
    }
    __syncthreads();

    // ---- 4) band blocks for both rows ----
    int q0 = tid << 2;
#pragma unroll
    for (int rr2 = 0; rr2 < 2; rr2++) {
        int p = p0 + rr2;
        float4* rowp = (float4*)(out + (size_t)(r0 + rr2) * TN);
        const float* bd = sBand[rr2];
        int d0 = q0 - p;

        {   // diag block i: D[d+66], valid d in [-66,66]
            float4 v = z;
            if (d0 + 3 >= -66 && d0 <= 66) {
                v.x = ((unsigned)(d0 + 66)     <= 132u) ? bd[d0 + 66]     : 0.0f;
                v.y = ((unsigned)(d0 + 67)     <= 132u) ? bd[d0 + 67]     : 0.0f;
                v.z = ((unsigned)(d0 + 68)     <= 132u) ? bd[d0 + 68]     : 0.0f;
                v.w = ((unsigned)(d0 + 69)     <= 132u) ? bd[d0 + 69]     : 0.0f;
            }
            __stcs(rowp + i * 256 + tid, v);
        }
        if (i > 0) {                // left offdiag: L[d+33], d in [-33,33]
            float4 v = z;
            if (d0 + 3 >= -33 && d0 <= 33) {
                v.x = ((unsigned)(d0 + 33) <= 66u) ? bd[136 + d0 + 33] : 0.0f;
                v.y = ((unsigned)(d0 + 34) <= 66u) ? bd[136 + d0 + 34] : 0.0f;
                v.z = ((unsigned)(d0 + 35) <= 66u) ? bd[136 + d0 + 35] : 0.0f;
                v.w = ((unsigned)(d0 + 36) <= 66u) ? bd[136 + d0 + 36] : 0.0f;
            }
            __stcs(rowp + (i - 1) * 256 + tid, v);
        }
        if (i < 8) {                // right offdiag: R[d+33]
            float4 v = z;
            if (d0 + 3 >= -33 && d0 <= 33) {
                v.x = ((unsigned)(d0 + 33) <= 66u) ? bd[204 + d0 + 33] : 0.0f;
                v.y = ((unsigned)(d0 + 34) <= 66u) ? bd[204 + d0 + 34] : 0.0f;
                v.z = ((unsigned)(d0 + 35) <= 66u) ? bd[204 + d0 + 35] : 0.0f;
                v.w = ((unsigned)(d0 + 36) <= 66u) ? bd[204 + d0 + 36] : 0.0f;
            }
            __stcs(rowp + (i + 1) * 256 + tid, v);
        }
    }
}

// ---------------------------------------------------------------------------
// Launcher. Inputs: kappa, m, H, tau (unused). Output: fp32 [1, 9216, 9216].
// ---------------------------------------------------------------------------
extern "C" void kernel_launch(void* const* d_in, const int* in_sizes, int n_in,
                              void* d_out, int out_size) {
    const float* kappa = (const float*)d_in[0];
    const float* m     = (const float*)d_in[1];
    const float* H     = (const float*)d_in[2];
    float* out = (float*)d_out;

    k_all<<<TN / 2, 256>>>(kappa, m, H, out);
}